// round 10
// baseline (speedup 1.0000x reference)
#include <cuda_runtime.h>
#include <math.h>

#define B 64
#define S 512
#define H 768
#define K 64

// Scratch
__device__ float g_scores[3 * B * K];
__device__ float g_pooled[3 * B * H];

// ---------------------------------------------------------------------------
// K1: raw scores[j] = dot(G0, Gj), j < len only. grid (B, 3, 4), block 256.
// ---------------------------------------------------------------------------
__global__ void __launch_bounds__(256)
score_kernel(const float* __restrict__ seq,
             const int* __restrict__ idx0, const int* __restrict__ len0,
             const int* __restrict__ idx1, const int* __restrict__ len1,
             const int* __restrict__ idx2, const int* __restrict__ len2,
             const float* __restrict__ bc0,
             const float* __restrict__ bc1,
             const float* __restrict__ bc2,
             float* __restrict__ out) {
    int b  = blockIdx.x;
    int t  = blockIdx.y;
    int jt = blockIdx.z;           // 16 j's per block
    const int* idxp = (t == 0) ? idx0 : (t == 1) ? idx1 : idx2;
    const int* lenp = (t == 0) ? len0 : (t == 1) ? len1 : len2;

    __shared__ float4 g0s[192];    // row 0 (768 floats)
    __shared__ int sidx[16];
    __shared__ int si0;

    int tid  = threadIdx.x;
    int wid  = tid >> 5;
    int lane = tid & 31;

    // bias init (layout: rel 64x9 | nov 64x3 | dir 64x3)
    if (b == 0 && t == 0 && jt == 0) {
        for (int i = tid; i < 960; i += 256) {
            float v;
            if (i < 576)      v = bc0[i % 9];
            else if (i < 768) v = bc1[(i - 576) % 3];
            else              v = bc2[(i - 768) % 3];
            out[i] = v;
        }
    }

    int len = lenp[b];
    int j0  = jt * 16;
    if (j0 >= len) return;          // block-uniform early out (bias done above)

    if (tid < 16) sidx[tid] = idxp[b * K + j0 + tid];
    if (tid == 16) si0 = idxp[b * K];
    __syncthreads();

    const float* seqb = seq + (size_t)b * S * H;

    if (tid < 192) g0s[tid] = ((const float4*)(seqb + (size_t)si0 * H))[tid];
    __syncthreads();

    bool doa = (j0 + wid)     < len;
    bool dob = (j0 + wid + 8) < len;
    const float4* ga = (const float4*)(seqb + (size_t)sidx[doa ? wid : 0] * H);
    const float4* gb = (const float4*)(seqb + (size_t)sidx[dob ? wid + 8 : 0] * H);

    if (!doa) return;  // warp-uniform; no further barriers below

    float4 av[6], bv[6];
    if (dob) {
        #pragma unroll
        for (int i = 0; i < 6; i++) { av[i] = ga[lane + 32 * i]; bv[i] = gb[lane + 32 * i]; }
    } else {
        #pragma unroll
        for (int i = 0; i < 6; i++) { av[i] = ga[lane + 32 * i]; bv[i] = make_float4(0,0,0,0); }
    }

    float sa = 0.f, sb = 0.f;
    #pragma unroll
    for (int i = 0; i < 6; i++) {
        float4 g0v = g0s[lane + 32 * i];
        sa += g0v.x * av[i].x + g0v.y * av[i].y
            + g0v.z * av[i].z + g0v.w * av[i].w;
        sb += g0v.x * bv[i].x + g0v.y * bv[i].y
            + g0v.z * bv[i].z + g0v.w * bv[i].w;
    }
    #pragma unroll
    for (int o = 16; o; o >>= 1) {
        sa += __shfl_xor_sync(0xffffffffu, sa, o);
        sb += __shfl_xor_sync(0xffffffffu, sb, o);
    }
    if (lane == 0) {
        float* dst = &g_scores[((size_t)t * B + b) * K + j0];
        dst[wid] = sa;
        if (dob) dst[wid + 8] = sb;
    }
}

// ---------------------------------------------------------------------------
// K2: softmax + weighted sum (j < len). grid (B, 3, 4 htiles of 192), block 192.
// ---------------------------------------------------------------------------
__global__ void pool_kernel(const float* __restrict__ seq,
                            const int* __restrict__ idx0, const int* __restrict__ len0,
                            const int* __restrict__ idx1, const int* __restrict__ len1,
                            const int* __restrict__ idx2, const int* __restrict__ len2) {
    int b  = blockIdx.x;
    int t  = blockIdx.y;
    int h0 = blockIdx.z * 192;
    const int* idxp = (t == 0) ? idx0 : (t == 1) ? idx1 : idx2;
    const int* lenp = (t == 0) ? len0 : (t == 1) ? len1 : len2;

    __shared__ float prob[K];
    __shared__ int   sidx[K];

    int tid  = threadIdx.x;
    int lane = tid & 31;
    int len  = lenp[b];

    if (tid < K) sidx[tid] = idxp[b * K + tid];

    if (tid < 32) {
        const float* sc = &g_scores[((size_t)t * B + b) * K];
        float sa = (lane      < len) ? sc[lane]      : -1e30f;
        float sb = (lane + 32 < len) ? sc[lane + 32] : -1e30f;
        float m = fmaxf(sa, sb);
        #pragma unroll
        for (int o = 16; o; o >>= 1) m = fmaxf(m, __shfl_xor_sync(0xffffffffu, m, o));
        float ea = (lane      < len) ? expf(sa - m) : 0.f;
        float eb = (lane + 32 < len) ? expf(sb - m) : 0.f;
        float sum = ea + eb;
        #pragma unroll
        for (int o = 16; o; o >>= 1) sum += __shfl_xor_sync(0xffffffffu, sum, o);
        float inv = (sum > 0.f) ? (1.0f / sum) : 0.f;
        prob[lane]      = ea * inv;
        prob[lane + 32] = eb * inv;
    }
    __syncthreads();

    const float* base = seq + (size_t)b * S * H + h0 + tid;
    float acc = 0.f;
    #pragma unroll 16
    for (int j = 0; j < len; j++) {
        acc += prob[j] * base[(size_t)sidx[j] * H];
    }
    if (len == 0) acc = base[0];
    g_pooled[((size_t)t * B + b) * H + h0 + tid] = acc;
}

// ---------------------------------------------------------------------------
// K3: h = tanh(P @ Wd^T + bd) + fused classifier.
// grid (12 rtiles of 64, 4 btiles of 16, 3), block 256 (8 warps).
// Warp = (rg, bg): rg = wid>>2 (rows rg*32+lane), bg = wid&3 (batches 4bg..+3).
// W streams gmem->registers (lane owns its row, contiguous LDG.128s);
// P staged ONCE transposed in dynamic smem; no syncs inside the k loop.
// Per kk per SM: 8 LDS phases, 8 FMA cycles -> FMA-balanced.
// ---------------------------------------------------------------------------
#define DENSE_SMEM ((H * 16 + 16 * 66) * sizeof(float))   // Pt + Hs = 53376 B

__global__ void __launch_bounds__(256)
dense_kernel(const float* __restrict__ Wd0, const float* __restrict__ bd0,
             const float* __restrict__ Wd1, const float* __restrict__ bd1,
             const float* __restrict__ Wd2, const float* __restrict__ bd2,
             const float* __restrict__ Wc0,
             const float* __restrict__ Wc1,
             const float* __restrict__ Wc2,
             float* __restrict__ out) {
    extern __shared__ float dsm[];
    float* Pt = dsm;               // [768][16], Pt[k*16 + bb]
    float* Hs = dsm + H * 16;      // [16][66],  Hs[bb*66 + r]

    int t = blockIdx.z;
    const float* Wd = (t == 0) ? Wd0 : (t == 1) ? Wd1 : Wd2;
    const float* bd = (t == 0) ? bd0 : (t == 1) ? bd1 : bd2;
    const float* Wc = (t == 0) ? Wc0 : (t == 1) ? Wc1 : Wc2;
    int nlab   = (t == 0) ? 9 : 3;
    int outoff = (t == 0) ? 0 : (t == 1) ? B * 9 : B * 9 + B * 3;

    int r0 = blockIdx.x * 64;
    int b0 = blockIdx.y * 16;

    int tid  = threadIdx.x;
    int wid  = tid >> 5;
    int lane = tid & 31;
    int rg   = wid >> 2;          // 0/1: row group
    int bg   = wid & 3;           // 0..3: batch group (batches 4bg..4bg+3)
    int row  = rg * 32 + lane;    // 0..63 within tile

    const float* P = g_pooled + (size_t)t * B * H;

    // ---- stage P transposed, once ----
    #pragma unroll
    for (int i = 0; i < 48; i++) {
        int bb = i / 3;
        int k  = (i - 3 * bb) * 256 + tid;
        Pt[k * 16 + bb] = P[(size_t)(b0 + bb) * H + k];
    }
    __syncthreads();

    // ---- main loop: W gmem->regs, P smem broadcast ----
    const float4* Wrow = (const float4*)(Wd + (size_t)(r0 + row) * H);
    float acc0 = 0.f, acc1 = 0.f, acc2 = 0.f, acc3 = 0.f;

    for (int k0 = 0; k0 < H; k0 += 32) {
        float4 w[8];
        #pragma unroll
        for (int i = 0; i < 8; i++) w[i] = Wrow[(k0 >> 2) + i];

        #pragma unroll
        for (int i = 0; i < 8; i++) {
            #pragma unroll
            for (int u = 0; u < 4; u++) {
                float  wv = (&w[i].x)[u];
                float4 pv = *(const float4*)&Pt[(k0 + 4 * i + u) * 16 + 4 * bg];
                acc0 += wv * pv.x;
                acc1 += wv * pv.y;
                acc2 += wv * pv.z;
                acc3 += wv * pv.w;
            }
        }
    }

    // ---- epilogue: tanh + bias -> Hs ----
    float bdr = __ldg(&bd[r0 + row]);
    Hs[(4 * bg + 0) * 66 + row] = tanhf(acc0 + bdr);
    Hs[(4 * bg + 1) * 66 + row] = tanhf(acc1 + bdr);
    Hs[(4 * bg + 2) * 66 + row] = tanhf(acc2 + bdr);
    Hs[(4 * bg + 3) * 66 + row] = tanhf(acc3 + bdr);
    __syncthreads();

    // ---- fused classifier: warp wid handles batches 2wid, 2wid+1 ----
    #pragma unroll
    for (int bb = 0; bb < 2; bb++) {
        int bl = 2 * wid + bb;
        float h0v = Hs[bl * 66 + lane];
        float h1v = Hs[bl * 66 + lane + 32];
        for (int l = 0; l < nlab; l++) {
            const float* wr = Wc + (size_t)l * H + r0;
            float s = h0v * __ldg(wr + lane) + h1v * __ldg(wr + lane + 32);
            #pragma unroll
            for (int o = 16; o; o >>= 1) s += __shfl_xor_sync(0xffffffffu, s, o);
            if (lane == 0)
                atomicAdd(&out[outoff + (b0 + bl) * nlab + l], s);
        }
    }
}

// ---------------------------------------------------------------------------
extern "C" void kernel_launch(void* const* d_in, const int* in_sizes, int n_in,
                              void* d_out, int out_size) {
    const float* seq      = (const float*)d_in[0];
    const int*   rel_idx  = (const int*)d_in[1];
    const int*   rel_len  = (const int*)d_in[2];
    const int*   nov_idx  = (const int*)d_in[3];
    const int*   nov_len  = (const int*)d_in[4];
    const int*   dir_idx  = (const int*)d_in[5];
    const int*   dir_len  = (const int*)d_in[6];
    const float* rel_dW   = (const float*)d_in[7];
    const float* rel_db   = (const float*)d_in[8];
    const float* rel_cW   = (const float*)d_in[9];
    const float* rel_cb   = (const float*)d_in[10];
    const float* nov_dW   = (const float*)d_in[11];
    const float* nov_db   = (const float*)d_in[12];
    const float* nov_cW   = (const float*)d_in[13];
    const float* nov_cb   = (const float*)d_in[14];
    const float* dir_dW   = (const float*)d_in[15];
    const float* dir_db   = (const float*)d_in[16];
    const float* dir_cW   = (const float*)d_in[17];
    const float* dir_cb   = (const float*)d_in[18];
    float* out = (float*)d_out;

    static int smem_set = 0;
    if (!smem_set) {
        cudaFuncSetAttribute(dense_kernel,
                             cudaFuncAttributeMaxDynamicSharedMemorySize,
                             DENSE_SMEM);
        smem_set = 1;
    }

    score_kernel<<<dim3(B, 3, 4), 256>>>(seq, rel_idx, rel_len, nov_idx, nov_len,
                                         dir_idx, dir_len,
                                         rel_cb, nov_cb, dir_cb, out);
    pool_kernel<<<dim3(B, 3, 4), 192>>>(seq, rel_idx, rel_len, nov_idx, nov_len,
                                        dir_idx, dir_len);
    dense_kernel<<<dim3(12, 4, 3), 256, DENSE_SMEM>>>(rel_dW, rel_db, nov_dW, nov_db,
                                                      dir_dW, dir_db,
                                                      rel_cW, nov_cW, dir_cW, out);
}

// round 11
// speedup vs baseline: 1.4495x; 1.4495x over previous
#include <cuda_runtime.h>
#include <math.h>
#include <stdint.h>

#define B 64
#define S 512
#define H 768
#define K 64

// Scratch
__device__ float g_scores[3 * B * K];
__device__ float g_pooled[3 * B * H];

__device__ __forceinline__ void cp16(void* dst_smem, const void* src) {
    uint32_t d = (uint32_t)__cvta_generic_to_shared(dst_smem);
    asm volatile("cp.async.cg.shared.global [%0], [%1], 16;" :: "r"(d), "l"(src) : "memory");
}
__device__ __forceinline__ void cp_commit() {
    asm volatile("cp.async.commit_group;" ::: "memory");
}
template<int N> __device__ __forceinline__ void cp_wait() {
    asm volatile("cp.async.wait_group %0;" :: "n"(N) : "memory");
}

// ---------------------------------------------------------------------------
// K1: raw scores[j] = dot(G0, Gj), j < len only. grid (B, 3, 8), block 128.
// 8 j's per block (4 warps x 2 j). Finer raggedness granularity, 1536 blocks.
// Block (0,0,0) also initializes out[] with classifier biases.
// ---------------------------------------------------------------------------
__global__ void __launch_bounds__(128)
score_kernel(const float* __restrict__ seq,
             const int* __restrict__ idx0, const int* __restrict__ len0,
             const int* __restrict__ idx1, const int* __restrict__ len1,
             const int* __restrict__ idx2, const int* __restrict__ len2,
             const float* __restrict__ bc0,
             const float* __restrict__ bc1,
             const float* __restrict__ bc2,
             float* __restrict__ out) {
    int b  = blockIdx.x;
    int t  = blockIdx.y;
    int jt = blockIdx.z;           // 8 j's per block
    const int* idxp = (t == 0) ? idx0 : (t == 1) ? idx1 : idx2;
    const int* lenp = (t == 0) ? len0 : (t == 1) ? len1 : len2;

    __shared__ float4 g0s[192];    // row 0 (768 floats)
    __shared__ int sidx[8];
    __shared__ int si0;

    int tid  = threadIdx.x;
    int wid  = tid >> 5;
    int lane = tid & 31;

    // bias init (layout: rel 64x9 | nov 64x3 | dir 64x3)
    if (b == 0 && t == 0 && jt == 0) {
        for (int i = tid; i < 960; i += 128) {
            float v;
            if (i < 576)      v = bc0[i % 9];
            else if (i < 768) v = bc1[(i - 576) % 3];
            else              v = bc2[(i - 768) % 3];
            out[i] = v;
        }
    }

    int len = lenp[b];
    int j0  = jt * 8;
    if (j0 >= len) return;          // block-uniform early out (bias done above)

    if (tid < 8)  sidx[tid] = idxp[b * K + j0 + tid];
    if (tid == 8) si0 = idxp[b * K];
    __syncthreads();

    const float* seqb = seq + (size_t)b * S * H;

    g0s[tid] = ((const float4*)(seqb + (size_t)si0 * H))[tid];
    if (tid < 64) g0s[tid + 128] = ((const float4*)(seqb + (size_t)si0 * H))[tid + 128];
    __syncthreads();

    bool doa = (j0 + wid)     < len;
    bool dob = (j0 + wid + 4) < len;
    // masked rows alias row sidx[0] (valid memory, result discarded)
    const float4* ga = (const float4*)(seqb + (size_t)sidx[doa ? wid : 0] * H);
    const float4* gb = (const float4*)(seqb + (size_t)sidx[dob ? wid + 4 : 0] * H);

    if (!doa) return;  // warp-uniform; no further barriers below

    float4 av[6], bv[6];
    if (dob) {
        #pragma unroll
        for (int i = 0; i < 6; i++) { av[i] = ga[lane + 32 * i]; bv[i] = gb[lane + 32 * i]; }
    } else {
        #pragma unroll
        for (int i = 0; i < 6; i++) { av[i] = ga[lane + 32 * i]; bv[i] = make_float4(0,0,0,0); }
    }

    float sa = 0.f, sb = 0.f;
    #pragma unroll
    for (int i = 0; i < 6; i++) {
        float4 g0v = g0s[lane + 32 * i];
        sa += g0v.x * av[i].x + g0v.y * av[i].y
            + g0v.z * av[i].z + g0v.w * av[i].w;
        sb += g0v.x * bv[i].x + g0v.y * bv[i].y
            + g0v.z * bv[i].z + g0v.w * bv[i].w;
    }
    #pragma unroll
    for (int o = 16; o; o >>= 1) {
        sa += __shfl_xor_sync(0xffffffffu, sa, o);
        sb += __shfl_xor_sync(0xffffffffu, sb, o);
    }
    if (lane == 0) {
        float* dst = &g_scores[((size_t)t * B + b) * K + j0];
        dst[wid] = sa;
        if (dob) dst[wid + 4] = sb;
    }
}

// ---------------------------------------------------------------------------
// K2: softmax + weighted sum (j < len). grid (B, 3, 4 htiles of 192), block 192.
// ---------------------------------------------------------------------------
__global__ void pool_kernel(const float* __restrict__ seq,
                            const int* __restrict__ idx0, const int* __restrict__ len0,
                            const int* __restrict__ idx1, const int* __restrict__ len1,
                            const int* __restrict__ idx2, const int* __restrict__ len2) {
    int b  = blockIdx.x;
    int t  = blockIdx.y;
    int h0 = blockIdx.z * 192;
    const int* idxp = (t == 0) ? idx0 : (t == 1) ? idx1 : idx2;
    const int* lenp = (t == 0) ? len0 : (t == 1) ? len1 : len2;

    __shared__ float prob[K];
    __shared__ int   sidx[K];

    int tid  = threadIdx.x;
    int lane = tid & 31;
    int len  = lenp[b];

    if (tid < K) sidx[tid] = idxp[b * K + tid];

    if (tid < 32) {
        const float* sc = &g_scores[((size_t)t * B + b) * K];
        float sa = (lane      < len) ? sc[lane]      : -1e30f;
        float sb = (lane + 32 < len) ? sc[lane + 32] : -1e30f;
        float m = fmaxf(sa, sb);
        #pragma unroll
        for (int o = 16; o; o >>= 1) m = fmaxf(m, __shfl_xor_sync(0xffffffffu, m, o));
        float ea = (lane      < len) ? expf(sa - m) : 0.f;
        float eb = (lane + 32 < len) ? expf(sb - m) : 0.f;
        float sum = ea + eb;
        #pragma unroll
        for (int o = 16; o; o >>= 1) sum += __shfl_xor_sync(0xffffffffu, sum, o);
        float inv = (sum > 0.f) ? (1.0f / sum) : 0.f;
        prob[lane]      = ea * inv;
        prob[lane + 32] = eb * inv;
    }
    __syncthreads();

    const float* base = seq + (size_t)b * S * H + h0 + tid;
    float acc = 0.f;
    #pragma unroll 16
    for (int j = 0; j < len; j++) {
        acc += prob[j] * base[(size_t)sidx[j] * H];
    }
    if (len == 0) acc = base[0];
    g_pooled[((size_t)t * B + b) * H + h0 + tid] = acc;
}

// ---------------------------------------------------------------------------
// K3: h = tanh(P @ Wd^T + bd) + fused classifier.
// grid (12 rtiles of 64, 4 btiles of 16, 3), block 256 (8 warps).
// Warp wid covers rows 8*wid..8*wid+7 x ALL 16 batches:
//   lane: row = 8*wid + (lane>>2), batches 4*(lane&3)..+3.
// Per kk per warp: 1 scalar LDS (8 distinct banks) + 1 broadcast LDS.128
//   -> crossbar ~6 cyc/kk/SM vs FMA 16 cyc/kk/SM: FMA-bound.
// W tiles double-buffered via cp.async (no staging registers, hidden latency).
// P staged once transposed.
// ---------------------------------------------------------------------------
#define WPAD 36
#define DENSE_SMEM ((H * 16 + 2 * 64 * WPAD + 16 * 66) * sizeof(float))  // 71808 B

__global__ void __launch_bounds__(256)
dense_kernel(const float* __restrict__ Wd0, const float* __restrict__ bd0,
             const float* __restrict__ Wd1, const float* __restrict__ bd1,
             const float* __restrict__ Wd2, const float* __restrict__ bd2,
             const float* __restrict__ Wc0,
             const float* __restrict__ Wc1,
             const float* __restrict__ Wc2,
             float* __restrict__ out) {
    extern __shared__ float dsm[];
    float* Pt = dsm;                        // [768][16]
    float* Ws = dsm + H * 16;               // [2][64][WPAD]
    float* Hs = Ws + 2 * 64 * WPAD;         // [16][66]

    int t = blockIdx.z;
    const float* Wd = (t == 0) ? Wd0 : (t == 1) ? Wd1 : Wd2;
    const float* bd = (t == 0) ? bd0 : (t == 1) ? bd1 : bd2;
    const float* Wc = (t == 0) ? Wc0 : (t == 1) ? Wc1 : Wc2;
    int nlab   = (t == 0) ? 9 : 3;
    int outoff = (t == 0) ? 0 : (t == 1) ? B * 9 : B * 9 + B * 3;

    int r0 = blockIdx.x * 64;
    int b0 = blockIdx.y * 16;

    int tid  = threadIdx.x;
    int wid  = tid >> 5;
    int lane = tid & 31;
    int row  = 8 * wid + (lane >> 2);   // 0..63
    int bg   = lane & 3;                // batches 4bg..4bg+3

    const float* P = g_pooled + (size_t)t * B * H;

    // staging map for one W k-tile (64 rows x 32 kk = 512 float4s, 2/thread):
    //   f4id = tid + 256*i -> r = f4id>>3, c4 = f4id&7
    //   gmem: Wd[(r0+r)*H + k0 + 4*c4] (16B contig), smem: Ws[buf][r][4*c4]
    int sr  = tid >> 3;
    int sc4 = tid & 7;

    // prologue: issue tile 0
    {
        const float* src = Wd + (size_t)(r0 + sr) * H + 4 * sc4;
        cp16(&Ws[sr * WPAD + 4 * sc4], src);
        cp16(&Ws[(sr + 32) * WPAD + 4 * sc4], src + (size_t)32 * H);
        cp_commit();
    }

    // stage P transposed, once (overlaps with tile-0 cp.async)
    #pragma unroll
    for (int i = 0; i < 48; i++) {
        int bb = i / 3;
        int k  = (i - 3 * bb) * 256 + tid;
        Pt[k * 16 + bb] = P[(size_t)(b0 + bb) * H + k];
    }

    float acc0 = 0.f, acc1 = 0.f, acc2 = 0.f, acc3 = 0.f;
    const int NT = H / 32;   // 24 tiles

    for (int it = 0; it < NT; it++) {
        if (it + 1 < NT) {
            int k0n = (it + 1) * 32;
            float* dstb = Ws + ((it + 1) & 1) * 64 * WPAD;
            const float* src = Wd + (size_t)(r0 + sr) * H + k0n + 4 * sc4;
            cp16(&dstb[sr * WPAD + 4 * sc4], src);
            cp16(&dstb[(sr + 32) * WPAD + 4 * sc4], src + (size_t)32 * H);
            cp_commit();
            cp_wait<1>();
        } else {
            cp_wait<0>();
        }
        __syncthreads();

        const float* Wb = Ws + (it & 1) * 64 * WPAD + row * WPAD;
        int k0 = it * 32;
        #pragma unroll
        for (int kk = 0; kk < 32; kk++) {
            float  wv = Wb[kk];
            float4 pv = *(const float4*)&Pt[(k0 + kk) * 16 + 4 * bg];
            acc0 += wv * pv.x;
            acc1 += wv * pv.y;
            acc2 += wv * pv.z;
            acc3 += wv * pv.w;
        }
        __syncthreads();
    }

    // epilogue: tanh + bias -> Hs
    float bdr = __ldg(&bd[r0 + row]);
    Hs[(4 * bg + 0) * 66 + row] = tanhf(acc0 + bdr);
    Hs[(4 * bg + 1) * 66 + row] = tanhf(acc1 + bdr);
    Hs[(4 * bg + 2) * 66 + row] = tanhf(acc2 + bdr);
    Hs[(4 * bg + 3) * 66 + row] = tanhf(acc3 + bdr);
    __syncthreads();

    // fused classifier: warp wid handles batches 2wid, 2wid+1
    #pragma unroll
    for (int bb = 0; bb < 2; bb++) {
        int bl = 2 * wid + bb;
        float h0v = Hs[bl * 66 + lane];
        float h1v = Hs[bl * 66 + lane + 32];
        for (int l = 0; l < nlab; l++) {
            const float* wr = Wc + (size_t)l * H + r0;
            float s = h0v * __ldg(wr + lane) + h1v * __ldg(wr + lane + 32);
            #pragma unroll
            for (int o = 16; o; o >>= 1) s += __shfl_xor_sync(0xffffffffu, s, o);
            if (lane == 0)
                atomicAdd(&out[outoff + (b0 + bl) * nlab + l], s);
        }
    }
}

// ---------------------------------------------------------------------------
extern "C" void kernel_launch(void* const* d_in, const int* in_sizes, int n_in,
                              void* d_out, int out_size) {
    const float* seq      = (const float*)d_in[0];
    const int*   rel_idx  = (const int*)d_in[1];
    const int*   rel_len  = (const int*)d_in[2];
    const int*   nov_idx  = (const int*)d_in[3];
    const int*   nov_len  = (const int*)d_in[4];
    const int*   dir_idx  = (const int*)d_in[5];
    const int*   dir_len  = (const int*)d_in[6];
    const float* rel_dW   = (const float*)d_in[7];
    const float* rel_db   = (const float*)d_in[8];
    const float* rel_cW   = (const float*)d_in[9];
    const float* rel_cb   = (const float*)d_in[10];
    const float* nov_dW   = (const float*)d_in[11];
    const float* nov_db   = (const float*)d_in[12];
    const float* nov_cW   = (const float*)d_in[13];
    const float* nov_cb   = (const float*)d_in[14];
    const float* dir_dW   = (const float*)d_in[15];
    const float* dir_db   = (const float*)d_in[16];
    const float* dir_cW   = (const float*)d_in[17];
    const float* dir_cb   = (const float*)d_in[18];
    float* out = (float*)d_out;

    static int smem_set = 0;
    if (!smem_set) {
        cudaFuncSetAttribute(dense_kernel,
                             cudaFuncAttributeMaxDynamicSharedMemorySize,
                             DENSE_SMEM);
        smem_set = 1;
    }

    score_kernel<<<dim3(B, 3, 8), 128>>>(seq, rel_idx, rel_len, nov_idx, nov_len,
                                         dir_idx, dir_len,
                                         rel_cb, nov_cb, dir_cb, out);
    pool_kernel<<<dim3(B, 3, 4), 192>>>(seq, rel_idx, rel_len, nov_idx, nov_len,
                                        dir_idx, dir_len);
    dense_kernel<<<dim3(12, 4, 3), 256, DENSE_SMEM>>>(rel_dW, rel_db, nov_dW, nov_db,
                                                      dir_dW, dir_db,
                                                      rel_cW, nov_cW, dir_cW, out);
}